// round 1
// baseline (speedup 1.0000x reference)
#include <cuda_runtime.h>
#include <cuda_bf16.h>
#include <cstdint>

#define BB   128
#define TT   256
#define NN   100
#define SS   7
#define GG   16
#define FF   35   // 5*SS
#define FP   36   // padded

__device__ __forceinline__ float sigf(float x) {
    return 1.0f / (1.0f + __expf(-x));
}
__device__ __forceinline__ float tanhfast(float x) {
    // tanh(x) = 2/(1+exp(-2x)) - 1, exp via MUFU.EX2 (rel err ~1e-6)
    return 2.0f / (1.0f + __expf(-2.0f * x)) - 1.0f;
}

// ============================================================================
// Kernel 1: lm MLP on xl = gather(x[:, T-1])  -> writes f into out[n*B + b]
// grid (4 b-blocks, 100 nodes), 256 threads. Dynamic smem: H1 [32][512] = 64KB
// ============================================================================
__global__ void __launch_bounds__(256) lm_mlp_kernel(
    const float* __restrict__ x,
    const float* __restrict__ W1, const float* __restrict__ b1,
    const float* __restrict__ W2, const float* __restrict__ b2,
    const float* __restrict__ W3, const float* __restrict__ b3,
    float* __restrict__ out)
{
    extern __shared__ float H1s_raw[];           // [32][512]
    float (*H1s)[512] = reinterpret_cast<float(*)[512]>(H1s_raw);
    __shared__ float xls[32][FP];
    __shared__ float H2s[32][257];
    __shared__ float sp[8][32];

    const int n    = blockIdx.y;
    const int bblk = blockIdx.x;
    const int tid  = threadIdx.x;
    const int offs[5] = {0, -10, 1, 10, -1};

    // gather xl (t = T-1)
    for (int idx = tid; idx < 32 * FP; idx += 256) {
        int b = idx / FP, f = idx % FP;
        float v = 0.0f;
        if (f < FF) {
            int o = f / SS, s = f % SS;
            int n2 = n + offs[o];
            if (n2 >= 0 && n2 < NN) {
                size_t gb = (size_t)(bblk * 32 + b);
                v = x[(gb * TT + (TT - 1)) * (NN * SS) + n2 * SS + s];
            }
        }
        xls[b][f] = v;
    }
    __syncthreads();

    // layer 1: (32x35) @ (35x512) -> H1 relu
    const float* W1g = W1 + (size_t)n * FF * 512;
    const float* b1g = b1 + (size_t)n * 512;
    #pragma unroll
    for (int pass = 0; pass < 2; pass++) {
        int h = tid + pass * 256;
        float acc[32];
        #pragma unroll
        for (int b = 0; b < 32; b++) acc[b] = 0.0f;
        #pragma unroll 5
        for (int f = 0; f < FF; f++) {
            float wv = W1g[f * 512 + h];
            #pragma unroll
            for (int b = 0; b < 32; b++) acc[b] = fmaf(xls[b][f], wv, acc[b]);
        }
        float bias = b1g[h];
        #pragma unroll
        for (int b = 0; b < 32; b++) H1s[b][h] = fmaxf(acc[b] + bias, 0.0f);
    }
    __syncthreads();

    // layer 2: (32x512) @ (512x256) -> H2 relu. Tile 8b x 4h per thread.
    {
        const float4* W2g = reinterpret_cast<const float4*>(W2 + (size_t)n * 512 * 256);
        const float*  b2g = b2 + (size_t)n * 256;
        int hg = tid & 63;    // 64 h-groups of 4
        int bg = tid >> 6;    // 4 b-groups of 8
        float acc[32];
        #pragma unroll
        for (int i = 0; i < 32; i++) acc[i] = 0.0f;
        for (int f = 0; f < 512; f++) {
            float4 wv = W2g[f * 64 + hg];
            float wc[4] = {wv.x, wv.y, wv.z, wv.w};
            float hv[8];
            #pragma unroll
            for (int bb = 0; bb < 8; bb++) hv[bb] = H1s[bg * 8 + bb][f];
            #pragma unroll
            for (int bb = 0; bb < 8; bb++)
                #pragma unroll
                for (int hh = 0; hh < 4; hh++)
                    acc[bb * 4 + hh] = fmaf(hv[bb], wc[hh], acc[bb * 4 + hh]);
        }
        #pragma unroll
        for (int hh = 0; hh < 4; hh++) {
            float bias = b2g[hg * 4 + hh];
            #pragma unroll
            for (int bb = 0; bb < 8; bb++)
                H2s[bg * 8 + bb][hg * 4 + hh] = fmaxf(acc[bb * 4 + hh] + bias, 0.0f);
        }
    }
    __syncthreads();

    // layer 3: (32x256) @ (256x1)
    {
        const float* W3g = W3 + (size_t)n * 256;
        int b = tid & 31, seg = tid >> 5;
        float s = 0.0f;
        #pragma unroll
        for (int c = 0; c < 32; c++)
            s = fmaf(H2s[b][seg * 32 + c], W3g[seg * 32 + c], s);
        sp[seg][b] = s;
    }
    __syncthreads();
    if (tid < 32) {
        float tot = b3[n];
        #pragma unroll
        for (int seg = 0; seg < 8; seg++) tot += sp[seg][tid];
        out[n * BB + bblk * 32 + tid] = tot;   // WRITE (kernel runs first)
    }
}

// ============================================================================
// Kernel 2: GRU over T steps + sc MLP. Adds q into out.
// grid (4 b-blocks, 100 nodes), 128 threads (4 warps; warp w owns j=4w..4w+3).
// ============================================================================
__global__ void __launch_bounds__(128) gru_kernel(
    const float* __restrict__ x,
    const float* __restrict__ Wih, const float* __restrict__ Whh,
    const float* __restrict__ bih, const float* __restrict__ bhh,
    const float* __restrict__ scW1, const float* __restrict__ scb1,
    const float* __restrict__ scW2, const float* __restrict__ scb2,
    const float* __restrict__ scW3, const float* __restrict__ scb3,
    float* __restrict__ out)
{
    __shared__ float sWih[48][FP];      // padded, float4-aligned rows (144B)
    __shared__ float sWhh[48][GG];
    __shared__ float sb[96];            // [0:48) bih, [48:96) bhh
    __shared__ float sh[2][32][17];     // double-buffered hidden state

    const int n    = blockIdx.y;
    const int bblk = blockIdx.x;
    const int tid  = threadIdx.x;
    const int lane = tid & 31;
    const int w    = tid >> 5;
    const int bg   = bblk * 32 + lane;

    // ---- stage weights ----
    for (int i = tid; i < 48 * FF; i += 128)
        sWih[i / FF][i % FF] = Wih[(size_t)n * 48 * FF + i];
    if (tid < 48) sWih[tid][FF] = 0.0f;
    for (int i = tid; i < 48 * GG; i += 128)
        sWhh[i >> 4][i & 15] = Whh[(size_t)n * 48 * GG + i];
    if (tid < 48) sb[tid] = bih[n * 48 + tid];
    if (tid >= 64 && tid < 112) sb[tid - 16] = bhh[n * 48 + (tid - 64)];
    for (int i = tid; i < 32 * GG; i += 128)
        sh[0][i >> 4][i & 15] = 0.0f;

    // neighbor base pointers for this lane's batch row
    const int offs[5] = {0, -10, 1, 10, -1};
    const float* px[5];
    bool vld[5];
    #pragma unroll
    for (int o = 0; o < 5; o++) {
        int n2 = n + offs[o];
        vld[o] = (n2 >= 0) && (n2 < NN);
        px[o]  = x + (size_t)bg * TT * (NN * SS) + (vld[o] ? n2 : 0) * SS;
    }
    __syncthreads();

    float xt[FP];
    xt[FF] = 0.0f;
    int cur = 0;

    for (int t = 0; t < TT; t++) {
        size_t toff = (size_t)t * (NN * SS);
        #pragma unroll
        for (int o = 0; o < 5; o++) {
            #pragma unroll
            for (int s = 0; s < SS; s++)
                xt[o * SS + s] = vld[o] ? px[o][toff + s] : 0.0f;
        }
        float hreg[GG];
        #pragma unroll
        for (int k = 0; k < GG; k++) hreg[k] = sh[cur][lane][k];

        #pragma unroll
        for (int jj = 0; jj < 4; jj++) {
            const int j = (w << 2) + jj;
            const float4* r0 = reinterpret_cast<const float4*>(sWih[j]);
            const float4* r1 = reinterpret_cast<const float4*>(sWih[j + 16]);
            const float4* r2 = reinterpret_cast<const float4*>(sWih[j + 32]);
            float ir = sb[j], iz = sb[j + 16], inn = sb[j + 32];
            #pragma unroll
            for (int f4 = 0; f4 < 9; f4++) {
                float4 a = r0[f4], c = r1[f4], d = r2[f4];
                ir  = fmaf(a.x, xt[4*f4+0], ir);  ir  = fmaf(a.y, xt[4*f4+1], ir);
                ir  = fmaf(a.z, xt[4*f4+2], ir);  ir  = fmaf(a.w, xt[4*f4+3], ir);
                iz  = fmaf(c.x, xt[4*f4+0], iz);  iz  = fmaf(c.y, xt[4*f4+1], iz);
                iz  = fmaf(c.z, xt[4*f4+2], iz);  iz  = fmaf(c.w, xt[4*f4+3], iz);
                inn = fmaf(d.x, xt[4*f4+0], inn); inn = fmaf(d.y, xt[4*f4+1], inn);
                inn = fmaf(d.z, xt[4*f4+2], inn); inn = fmaf(d.w, xt[4*f4+3], inn);
            }
            const float4* q0 = reinterpret_cast<const float4*>(sWhh[j]);
            const float4* q1 = reinterpret_cast<const float4*>(sWhh[j + 16]);
            const float4* q2 = reinterpret_cast<const float4*>(sWhh[j + 32]);
            float hr = sb[48 + j], hz = sb[64 + j], hn = sb[80 + j];
            #pragma unroll
            for (int k4 = 0; k4 < 4; k4++) {
                float4 a = q0[k4], c = q1[k4], d = q2[k4];
                hr = fmaf(a.x, hreg[4*k4+0], hr); hr = fmaf(a.y, hreg[4*k4+1], hr);
                hr = fmaf(a.z, hreg[4*k4+2], hr); hr = fmaf(a.w, hreg[4*k4+3], hr);
                hz = fmaf(c.x, hreg[4*k4+0], hz); hz = fmaf(c.y, hreg[4*k4+1], hz);
                hz = fmaf(c.z, hreg[4*k4+2], hz); hz = fmaf(c.w, hreg[4*k4+3], hz);
                hn = fmaf(d.x, hreg[4*k4+0], hn); hn = fmaf(d.y, hreg[4*k4+1], hn);
                hn = fmaf(d.z, hreg[4*k4+2], hn); hn = fmaf(d.w, hreg[4*k4+3], hn);
            }
            float r  = sigf(ir + hr);
            float z  = sigf(iz + hz);
            float nn = tanhfast(inn + r * hn);
            sh[cur ^ 1][lane][j] = (1.0f - z) * nn + z * hreg[j];
        }
        cur ^= 1;
        __syncthreads();
    }
    // final state is in sh[0] (T even)

    // ---- sc MLP epilogue ----
    float hT[GG];
    #pragma unroll
    for (int k = 0; k < GG; k++) hT[k] = sh[0][lane][k];

    const float* sW1 = scW1 + n * 256;
    #pragma unroll
    for (int jj = 0; jj < 4; jj++) {
        int j = (w << 2) + jj;
        float acc = scb1[n * GG + j];
        #pragma unroll
        for (int f = 0; f < GG; f++) acc = fmaf(hT[f], sW1[f * GG + j], acc);
        sh[1][lane][j] = fmaxf(acc, 0.0f);
    }
    __syncthreads();

    float g1[GG];
    #pragma unroll
    for (int k = 0; k < GG; k++) g1[k] = sh[1][lane][k];
    const float* sW2 = scW2 + n * 256;
    #pragma unroll
    for (int jj = 0; jj < 4; jj++) {
        int j = (w << 2) + jj;
        float acc = scb2[n * GG + j];
        #pragma unroll
        for (int f = 0; f < GG; f++) acc = fmaf(g1[f], sW2[f * GG + j], acc);
        sh[0][lane][j] = fmaxf(acc, 0.0f);
    }
    __syncthreads();

    if (w == 0) {
        float q = scb3[n];
        #pragma unroll
        for (int k = 0; k < GG; k++) q = fmaf(sh[0][lane][k], scW3[n * GG + k], q);
        int idx = n * BB + bg;
        out[idx] = out[idx] + q;   // lm kernel already wrote f
    }
}

// ============================================================================
extern "C" void kernel_launch(void* const* d_in, const int* in_sizes, int n_in,
                              void* d_out, int out_size) {
    const float* x      = (const float*)d_in[0];
    const float* lm_W1  = (const float*)d_in[1];
    const float* lm_b1  = (const float*)d_in[2];
    const float* lm_W2  = (const float*)d_in[3];
    const float* lm_b2  = (const float*)d_in[4];
    const float* lm_W3  = (const float*)d_in[5];
    const float* lm_b3  = (const float*)d_in[6];
    const float* gWih   = (const float*)d_in[7];
    const float* gWhh   = (const float*)d_in[8];
    const float* gbih   = (const float*)d_in[9];
    const float* gbhh   = (const float*)d_in[10];
    const float* scW1   = (const float*)d_in[11];
    const float* scb1   = (const float*)d_in[12];
    const float* scW2   = (const float*)d_in[13];
    const float* scb2   = (const float*)d_in[14];
    const float* scW3   = (const float*)d_in[15];
    const float* scb3   = (const float*)d_in[16];
    float* out = (float*)d_out;

    static int attr_set = 0;
    // idempotent + deterministic; not a stream op so safe under graph capture
    cudaFuncSetAttribute(lm_mlp_kernel,
                         cudaFuncAttributeMaxDynamicSharedMemorySize, 32 * 512 * 4);
    (void)attr_set;

    dim3 gridMlp(4, NN), blockMlp(256);
    lm_mlp_kernel<<<gridMlp, blockMlp, 32 * 512 * 4>>>(
        x, lm_W1, lm_b1, lm_W2, lm_b2, lm_W3, lm_b3, out);

    dim3 gridGru(4, NN), blockGru(128);
    gru_kernel<<<gridGru, blockGru>>>(
        x, gWih, gWhh, gbih, gbhh,
        scW1, scb1, scW2, scb2, scW3, scb3, out);
}

// round 2
// speedup vs baseline: 2.5667x; 2.5667x over previous
#include <cuda_runtime.h>
#include <cuda_bf16.h>
#include <cstdint>

#define BB   128
#define TT   256
#define NN   100
#define SS   7
#define GG   16
#define FF   35
#define FP   36   // padded feature count (row 35 zeroed)

typedef unsigned long long ull;

__device__ __forceinline__ ull fma2(ull a, ull b, ull c) {
    ull d; asm("fma.rn.f32x2 %0, %1, %2, %3;" : "=l"(d) : "l"(a), "l"(b), "l"(c));
    return d;
}
__device__ __forceinline__ ull add2(ull a, ull b) {
    ull d; asm("add.rn.f32x2 %0, %1, %2;" : "=l"(d) : "l"(a), "l"(b));
    return d;
}
__device__ __forceinline__ ull dup2(float w) {
    ull d; asm("mov.b64 %0, {%1, %1};" : "=l"(d) : "f"(w));
    return d;
}
__device__ __forceinline__ float plo(ull p) { return __int_as_float((int)(unsigned)p); }
__device__ __forceinline__ float phi(ull p) { return __int_as_float((int)(p >> 32)); }
__device__ __forceinline__ float pget(ull p, int h) { return h ? phi(p) : plo(p); }

__device__ __forceinline__ float sigf(float x) {
    return __fdividef(1.0f, 1.0f + __expf(-x));
}
__device__ __forceinline__ float tanhfast(float x) {
    return __fdividef(2.0f, 1.0f + __expf(-2.0f * x)) - 1.0f;
}

// ============================================================================
// Kernel 1: lm MLP on xl = gather(x[:, T-1])  -> WRITES f into out[n*B + b]
// grid (4 b-blocks of 32, 100 nodes), 256 threads.
// Dynamic smem: H1T [512][36] floats (transposed for batch-pair packing).
// ============================================================================
__global__ void __launch_bounds__(256) lm_mlp_kernel(
    const float* __restrict__ x,
    const float* __restrict__ W1, const float* __restrict__ b1,
    const float* __restrict__ W2, const float* __restrict__ b2,
    const float* __restrict__ W3, const float* __restrict__ b3,
    float* __restrict__ out)
{
    extern __shared__ __align__(16) float H1T[];      // [512][36]
    __shared__ __align__(16) float xls[32][FP];
    __shared__ __align__(16) float H2s[32][257];
    __shared__ float sp[8][32];

    const int n    = blockIdx.y;
    const int bblk = blockIdx.x;
    const int tid  = threadIdx.x;
    const int offs[5] = {0, -10, 1, 10, -1};

    // gather xl (t = T-1), coalesced-ish
    for (int idx = tid; idx < 32 * FP; idx += 256) {
        int b = idx / FP, f = idx % FP;
        float v = 0.0f;
        if (f < FF) {
            int o = f / SS, s = f % SS;
            int n2 = n + offs[o];
            if (n2 >= 0 && n2 < NN) {
                size_t gb = (size_t)(bblk * 32 + b);
                v = x[(gb * TT + (TT - 1)) * (NN * SS) + n2 * SS + s];
            }
        }
        xls[b][f] = v;
    }
    __syncthreads();

    // layer 1: (32x35) @ (35x512) -> H1T (transposed), relu
    const float* W1g = W1 + (size_t)n * FF * 512;
    const float* b1g = b1 + (size_t)n * 512;
    #pragma unroll
    for (int pass = 0; pass < 2; pass++) {
        int h = tid + pass * 256;
        float acc[32];
        #pragma unroll
        for (int b = 0; b < 32; b++) acc[b] = 0.0f;
        #pragma unroll 5
        for (int f = 0; f < FF; f++) {
            float wv = W1g[f * 512 + h];
            #pragma unroll
            for (int b = 0; b < 32; b++) acc[b] = fmaf(xls[b][f], wv, acc[b]);
        }
        float bias = b1g[h];
        #pragma unroll
        for (int b4 = 0; b4 < 8; b4++) {
            float4 v;
            v.x = fmaxf(acc[b4*4+0] + bias, 0.0f);
            v.y = fmaxf(acc[b4*4+1] + bias, 0.0f);
            v.z = fmaxf(acc[b4*4+2] + bias, 0.0f);
            v.w = fmaxf(acc[b4*4+3] + bias, 0.0f);
            *reinterpret_cast<float4*>(&H1T[h * FP + b4 * 4]) = v;
        }
    }
    __syncthreads();

    // layer 2: (32x512) @ (512x256) -> H2 relu. f32x2: 4h x 8b (4 pairs) tile.
    {
        const float4* W2g = reinterpret_cast<const float4*>(W2 + (size_t)n * 512 * 256);
        const float*  b2g = b2 + (size_t)n * 256;
        const int hg = tid & 63;    // 64 h-groups of 4
        const int bg = tid >> 6;    // 4 b-groups of 8 (4 pairs)
        ull acc[16];
        #pragma unroll
        for (int i = 0; i < 16; i++) acc[i] = 0ULL;
        #pragma unroll 2
        for (int f = 0; f < 512; f++) {
            float4 wv = W2g[f * 64 + hg];
            ull wd[4] = {dup2(wv.x), dup2(wv.y), dup2(wv.z), dup2(wv.w)};
            const ull* xp = reinterpret_cast<const ull*>(&H1T[f * FP + bg * 8]);
            ull x0 = xp[0], x1 = xp[1], x2 = xp[2], x3 = xp[3];
            #pragma unroll
            for (int hh = 0; hh < 4; hh++) {
                acc[hh*4+0] = fma2(x0, wd[hh], acc[hh*4+0]);
                acc[hh*4+1] = fma2(x1, wd[hh], acc[hh*4+1]);
                acc[hh*4+2] = fma2(x2, wd[hh], acc[hh*4+2]);
                acc[hh*4+3] = fma2(x3, wd[hh], acc[hh*4+3]);
            }
        }
        #pragma unroll
        for (int hh = 0; hh < 4; hh++) {
            float bias = b2g[hg * 4 + hh];
            #pragma unroll
            for (int pi = 0; pi < 4; pi++) {
                int b = bg * 8 + pi * 2;
                H2s[b    ][hg * 4 + hh] = fmaxf(plo(acc[hh*4+pi]) + bias, 0.0f);
                H2s[b + 1][hg * 4 + hh] = fmaxf(phi(acc[hh*4+pi]) + bias, 0.0f);
            }
        }
    }
    __syncthreads();

    // layer 3: (32x256) @ (256x1)
    {
        const float* W3g = W3 + (size_t)n * 256;
        int b = tid & 31, seg = tid >> 5;
        float s = 0.0f;
        #pragma unroll
        for (int c = 0; c < 32; c++)
            s = fmaf(H2s[b][seg * 32 + c], W3g[seg * 32 + c], s);
        sp[seg][b] = s;
    }
    __syncthreads();
    if (tid < 32) {
        float tot = b3[n];
        #pragma unroll
        for (int seg = 0; seg < 8; seg++) tot += sp[seg][tid];
        out[n * BB + bblk * 32 + tid] = tot;   // WRITE (this kernel runs first)
    }
}

// ============================================================================
// Kernel 2: GRU over T steps + sc MLP epilogue. ADDS q into out.
// grid (8 b-blocks of 16, 100 nodes), 64 threads = 16 j x 4 bgroups(4 batches).
// f32x2 packed math, transposed shared tiles, double buffering, 1 sync/step.
// ============================================================================
__global__ void __launch_bounds__(64) gru_kernel(
    const float* __restrict__ x,
    const float* __restrict__ Wih, const float* __restrict__ Whh,
    const float* __restrict__ bih, const float* __restrict__ bhh,
    const float* __restrict__ scW1, const float* __restrict__ scb1,
    const float* __restrict__ scW2, const float* __restrict__ scb2,
    const float* __restrict__ scW3, const float* __restrict__ scb3,
    float* __restrict__ out)
{
    __shared__ __align__(16) ull sWihT[FP * 48];   // [f][gate] dup pairs
    __shared__ __align__(16) ull sWhhT[GG * 48];   // [k][gate] dup pairs
    __shared__ __align__(16) ull sbihD[48];
    __shared__ __align__(16) ull sbhhD[48];
    __shared__ __align__(16) float xts[2][FP * 20];   // [buf][f][16b pad20]
    __shared__ __align__(16) float shh[2][GG * 20];   // [buf][k][16b pad20]

    const int n    = blockIdx.y;
    const int bblk = blockIdx.x;
    const int tid  = threadIdx.x;
    const int jq   = tid & 15;    // hidden unit
    const int bg   = tid >> 4;    // batch group (4 batches)
    const int bg4  = bg * 4;

    // ---- stage weights (duplicated pairs, transposed) ----
    const float* Wihg = Wih + (size_t)n * 48 * FF;
    for (int i = tid; i < 48 * FF; i += 64) {
        int g = i / FF, f = i % FF;
        sWihT[f * 48 + g] = dup2(Wihg[i]);
    }
    for (int i = tid; i < 48; i += 64) sWihT[FF * 48 + i] = 0ULL;  // pad row
    const float* Whhg = Whh + (size_t)n * 48 * GG;
    for (int i = tid; i < 48 * GG; i += 64) {
        int g = i >> 4, k = i & 15;
        sWhhT[k * 48 + g] = dup2(Whhg[i]);
    }
    if (tid < 48) {
        sbihD[tid] = dup2(bih[n * 48 + tid]);
        sbhhD[tid] = dup2(bhh[n * 48 + tid]);
    }
    for (int i = tid; i < GG * 20; i += 64) shh[0][i] = 0.0f;     // h0 = 0
    if (tid < 16) { xts[0][FF * 20 + tid] = 0.0f; xts[1][FF * 20 + tid] = 0.0f; }

    // ---- precompute x staging slots (9 per thread, coalesced) ----
    const int offs[5] = {0, -10, 1, 10, -1};
    int  gofs[9]; int sofs[9]; bool act[9]; bool vld[9];
    #pragma unroll
    for (int s9 = 0; s9 < 9; s9++) {
        int idx = tid + s9 * 64;
        act[s9] = (idx < 16 * FF);
        int b = idx / FF, f = idx % FF;
        if (!act[s9]) { b = 0; f = 0; }
        int o = f / SS, s = f % SS;
        int n2 = n + offs[o];
        vld[s9] = act[s9] && (n2 >= 0) && (n2 < NN);
        int gb = bblk * 16 + b;
        gofs[s9] = gb * (TT * NN * SS) + (vld[s9] ? (n2 * SS + s) : 0);
        sofs[s9] = f * 20 + b;
    }

    // stage t = 0
    #pragma unroll
    for (int s9 = 0; s9 < 9; s9++)
        if (act[s9]) xts[0][sofs[s9]] = vld[s9] ? x[gofs[s9]] : 0.0f;
    __syncthreads();

    // bias registers
    const ull bir = sbihD[jq], biz = sbihD[jq + 16], bin = sbihD[jq + 32];
    const ull bhr = sbhhD[jq], bhz = sbhhD[jq + 16], bhn = sbhhD[jq + 32];

    int cur = 0;
    for (int t = 0; t < TT; t++) {
        // prefetch t+1 into registers (hidden under compute)
        float xv[9];
        int tn = (t + 1 < TT) ? (t + 1) : (TT - 1);
        #pragma unroll
        for (int s9 = 0; s9 < 9; s9++)
            xv[s9] = vld[s9] ? x[gofs[s9] + tn * (NN * SS)] : 0.0f;

        const float* xc = xts[cur];
        const float* hc = shh[cur];

        ull ir0 = bir, ir1 = bir, iz0 = biz, iz1 = biz, in0 = bin, in1 = bin;
        #pragma unroll
        for (int f = 0; f < FP; f++) {
            const ull* xp = reinterpret_cast<const ull*>(&xc[f * 20 + bg4]);
            ull x0 = xp[0], x1 = xp[1];
            ull wr = sWihT[f * 48 + jq];
            ull wz = sWihT[f * 48 + jq + 16];
            ull wn = sWihT[f * 48 + jq + 32];
            ir0 = fma2(x0, wr, ir0);  ir1 = fma2(x1, wr, ir1);
            iz0 = fma2(x0, wz, iz0);  iz1 = fma2(x1, wz, iz1);
            in0 = fma2(x0, wn, in0);  in1 = fma2(x1, wn, in1);
        }
        ull hr0 = bhr, hr1 = bhr, hz0 = bhz, hz1 = bhz, hn0 = bhn, hn1 = bhn;
        #pragma unroll
        for (int k = 0; k < GG; k++) {
            const ull* hp = reinterpret_cast<const ull*>(&hc[k * 20 + bg4]);
            ull h0 = hp[0], h1 = hp[1];
            ull wr = sWhhT[k * 48 + jq];
            ull wz = sWhhT[k * 48 + jq + 16];
            ull wn = sWhhT[k * 48 + jq + 32];
            hr0 = fma2(h0, wr, hr0);  hr1 = fma2(h1, wr, hr1);
            hz0 = fma2(h0, wz, hz0);  hz1 = fma2(h1, wz, hz1);
            hn0 = fma2(h0, wn, hn0);  hn1 = fma2(h1, wn, hn1);
        }

        // gates + state update for this thread's (j, 4 batches)
        ull ra[2] = {add2(ir0, hr0), add2(ir1, hr1)};
        ull za[2] = {add2(iz0, hz0), add2(iz1, hz1)};
        ull ia[2] = {in0, in1};
        ull ha[2] = {hn0, hn1};
        float4 hold = *reinterpret_cast<const float4*>(&hc[jq * 20 + bg4]);
        const float* hof = reinterpret_cast<const float*>(&hold);
        float4 hnew;
        float* hnf = reinterpret_cast<float*>(&hnew);
        #pragma unroll
        for (int i = 0; i < 4; i++) {
            int p = i >> 1, hf = i & 1;
            float r  = sigf(pget(ra[p], hf));
            float z  = sigf(pget(za[p], hf));
            float nv = tanhfast(pget(ia[p], hf) + r * pget(ha[p], hf));
            hnf[i] = nv + z * (hof[i] - nv);
        }
        *reinterpret_cast<float4*>(&shh[cur ^ 1][jq * 20 + bg4]) = hnew;

        // store prefetched x into next buffer
        float* xn = xts[cur ^ 1];
        #pragma unroll
        for (int s9 = 0; s9 < 9; s9++)
            if (act[s9]) xn[sofs[s9]] = xv[s9];

        __syncthreads();
        cur ^= 1;
    }
    // final hT is in shh[0] (T even)

    // ---- sc MLP epilogue (tiny) ----
    const float* W1g = scW1 + n * 256;
    {
        float b1v = scb1[n * GG + jq];
        #pragma unroll
        for (int i = 0; i < 4; i++) {
            int b = bg4 + i;
            float acc = b1v;
            #pragma unroll
            for (int k = 0; k < GG; k++)
                acc = fmaf(shh[0][k * 20 + b], W1g[k * 16 + jq], acc);
            shh[1][jq * 20 + b] = fmaxf(acc, 0.0f);
        }
    }
    __syncthreads();
    const float* W2g = scW2 + n * 256;
    {
        float b2v = scb2[n * GG + jq];
        #pragma unroll
        for (int i = 0; i < 4; i++) {
            int b = bg4 + i;
            float acc = b2v;
            #pragma unroll
            for (int k = 0; k < GG; k++)
                acc = fmaf(shh[1][k * 20 + b], W2g[k * 16 + jq], acc);
            shh[0][jq * 20 + b] = fmaxf(acc, 0.0f);
        }
    }
    __syncthreads();
    if (tid < 16) {
        int b = tid;
        float q = scb3[n];
        #pragma unroll
        for (int k = 0; k < GG; k++)
            q = fmaf(shh[0][k * 20 + b], scW3[n * GG + k], q);
        int idx = n * BB + bblk * 16 + b;
        out[idx] = out[idx] + q;   // lm kernel already wrote f
    }
}

// ============================================================================
extern "C" void kernel_launch(void* const* d_in, const int* in_sizes, int n_in,
                              void* d_out, int out_size) {
    const float* x      = (const float*)d_in[0];
    const float* lm_W1  = (const float*)d_in[1];
    const float* lm_b1  = (const float*)d_in[2];
    const float* lm_W2  = (const float*)d_in[3];
    const float* lm_b2  = (const float*)d_in[4];
    const float* lm_W3  = (const float*)d_in[5];
    const float* lm_b3  = (const float*)d_in[6];
    const float* gWih   = (const float*)d_in[7];
    const float* gWhh   = (const float*)d_in[8];
    const float* gbih   = (const float*)d_in[9];
    const float* gbhh   = (const float*)d_in[10];
    const float* scW1   = (const float*)d_in[11];
    const float* scb1   = (const float*)d_in[12];
    const float* scW2   = (const float*)d_in[13];
    const float* scb2   = (const float*)d_in[14];
    const float* scW3   = (const float*)d_in[15];
    const float* scb3   = (const float*)d_in[16];
    float* out = (float*)d_out;

    const int h1t_bytes = 512 * FP * 4;  // 73728
    cudaFuncSetAttribute(lm_mlp_kernel,
                         cudaFuncAttributeMaxDynamicSharedMemorySize, h1t_bytes);

    dim3 gridMlp(4, NN), blockMlp(256);
    lm_mlp_kernel<<<gridMlp, blockMlp, h1t_bytes>>>(
        x, lm_W1, lm_b1, lm_W2, lm_b2, lm_W3, lm_b3, out);

    dim3 gridGru(8, NN), blockGru(64);
    gru_kernel<<<gridGru, blockGru>>>(
        x, gWih, gWhh, gbih, gbhh,
        scW1, scb1, scW2, scb2, scW3, scb3, out);
}